// round 11
// baseline (speedup 1.0000x reference)
#include <cuda_runtime.h>
#include <cuda_bf16.h>
#include <cuda_fp16.h>
#include <stdint.h>

// Problem constants
#define BB 8
#define NN 2048
#define HH 512
#define NSEL 9
#define NLAYERS 3
#define LN_EPS 1e-5f

#define ADJ_WORDS 64
#define MTOT (BB*NN)        // 16384 rows

// ---------------- device scratch ----------------
__device__ uint32_t g_adj[BB * NN * ADJ_WORDS];     // 4 MB
__device__ float4   g_x4[BB * NN * (HH/4)];         // 32 MB current x (fp32, residual path)
__device__ __half   g_xh[MTOT * HH];                // 16 MB fp16 shadow of x (agg input)
__device__ __half   g_Ah[MTOT * HH];                // 16 MB agg fp16
__device__ __half   g_Wh[NLAYERS * HH * HH];        // W^T fp16  [l][n][k]

// ---------------- helpers (sm_80+ only) ----------------
__device__ __forceinline__ uint32_t smem_u32(const void* p) {
    uint32_t a;
    asm("{ .reg .u64 t; cvta.to.shared.u64 t, %1; cvt.u32.u64 %0, t; }" : "=r"(a) : "l"(p));
    return a;
}
__device__ __forceinline__ void ldm_x4(uint32_t* r, uint32_t addr) {
    asm volatile("ldmatrix.sync.aligned.m8n8.x4.shared.b16 {%0,%1,%2,%3}, [%4];"
                 : "=r"(r[0]), "=r"(r[1]), "=r"(r[2]), "=r"(r[3]) : "r"(addr));
}
__device__ __forceinline__ void mma_fp16(float* c, const uint32_t* a, const uint32_t* b) {
    asm volatile("mma.sync.aligned.m16n8k16.row.col.f32.f16.f16.f32 "
                 "{%0,%1,%2,%3}, {%4,%5,%6,%7}, {%8,%9}, {%0,%1,%2,%3};"
                 : "+f"(c[0]), "+f"(c[1]), "+f"(c[2]), "+f"(c[3])
                 : "r"(a[0]), "r"(a[1]), "r"(a[2]), "r"(a[3]), "r"(b[0]), "r"(b[1]));
}
__device__ __forceinline__ void cpa16(uint32_t s, const void* g) {
    asm volatile("cp.async.cg.shared.global [%0], [%1], 16;" :: "r"(s), "l"(g));
}

// ---------------- kernel 0: merged setup ----------------
// blocks [0,128): zero g_adj
// blocks [128,896): convw (3*16*16 tiles)
// blocks [896,1920): node_features fp32 -> g_xh fp16
__global__ void __launch_bounds__(256) setup_kernel(const float* __restrict__ W,
                                                    const float4* __restrict__ nf4) {
    __shared__ float tile[32][33];
    if (blockIdx.x < 128) {
        for (int j = blockIdx.x * 256 + threadIdx.x; j < BB * NN * ADJ_WORDS; j += 128 * 256)
            g_adj[j] = 0u;
        return;
    }
    if (blockIdx.x >= 896) {
        const int base = (blockIdx.x - 896) * 256 + threadIdx.x;
        for (int j = base; j < MTOT * (HH / 4); j += 1024 * 256) {
            const float4 v = nf4[j];
            __half2 h01 = __floats2half2_rn(v.x, v.y);
            __half2 h23 = __floats2half2_rn(v.z, v.w);
            ((__half2*)g_xh)[2 * j]     = h01;
            ((__half2*)g_xh)[2 * j + 1] = h23;
        }
        return;
    }
    const int bid = blockIdx.x - 128;
    const int l   = bid >> 8;            // 0..2
    const int rem = bid & 255;
    const int n0  = (rem & 15) * 32;
    const int k0  = (rem >> 4) * 32;
    const int tx  = threadIdx.x & 31;
    const int ty  = threadIdx.x >> 5;    // 0..7

    #pragma unroll
    for (int i = 0; i < 4; i++)
        tile[ty + i * 8][tx] = W[(size_t)l * HH * HH + (size_t)(k0 + ty + i * 8) * HH + n0 + tx];
    __syncthreads();

    #pragma unroll
    for (int i = 0; i < 4; i++) {
        const int n = n0 + ty + i * 8;
        const int k = k0 + tx;
        g_Wh[(size_t)l * HH * HH + (size_t)n * HH + k] = __float2half_rn(tile[tx][ty + i * 8]);
    }
}

// ---------------- kernel 1: warp-per-row top-k + adjacency build ----------------
__global__ void __launch_bounds__(256) topk_adj_kernel(const float2* __restrict__ coords) {
    __shared__ float2 sc[NN];
    const int b    = blockIdx.y;
    const int tid  = threadIdx.x;
    const int lane = tid & 31;
    const int wrp  = tid >> 5;                 // 0..7
    const int n    = blockIdx.x * 8 + wrp;

    const float2* cb = coords + (size_t)b * NN;
    for (int i = tid; i < NN; i += 256) sc[i] = cb[i];
    __syncthreads();

    const float xn = sc[n].x, yn = sc[n].y;
    const float sqn = __fadd_rn(__fmul_rn(xn, xn), __fmul_rn(yn, yn));

    unsigned long long top[NSEL];
    #pragma unroll
    for (int j = 0; j < NSEL; j++) top[j] = ~0ull;

    for (int m = lane; m < NN; m += 32) {
        const float xm = sc[m].x, ym = sc[m].y;
        const float sqm = __fadd_rn(__fmul_rn(xm, xm), __fmul_rn(ym, ym));
        const float dot = __fmaf_rn(yn, ym, __fmul_rn(xn, xm));
        const float d2  = __fsub_rn(__fadd_rn(sqn, sqm), __fmul_rn(2.0f, dot));
        uint32_t fb = __float_as_uint(d2);
        fb = (fb & 0x80000000u) ? ~fb : (fb | 0x80000000u);
        const unsigned long long k = ((unsigned long long)fb << 32) | (uint32_t)m;
        if (k < top[NSEL - 1]) {
            top[NSEL - 1] = k;
            #pragma unroll
            for (int j = NSEL - 1; j > 0; j--) {
                if (top[j] < top[j - 1]) {
                    unsigned long long t = top[j]; top[j] = top[j - 1]; top[j - 1] = t;
                }
            }
        }
    }

    int p = 0;
    for (int r = 0; r < NSEL; r++) {
        unsigned long long cand = (p < NSEL) ? top[p] : ~0ull;
        unsigned long long mn = cand;
        #pragma unroll
        for (int off = 16; off > 0; off >>= 1) {
            unsigned long long o = __shfl_xor_sync(0xffffffffu, mn, off);
            mn = (o < mn) ? o : mn;
        }
        if (cand == mn) p++;
        if (r > 0 && lane == 0) {
            const int m = (int)(mn & 0xffffffffu);
            atomicOr(&g_adj[((size_t)b * NN + n) * ADJ_WORDS + (m >> 5)], 1u << (m & 31));
            atomicOr(&g_adj[((size_t)b * NN + m) * ADJ_WORDS + (n >> 5)], 1u << (n & 31));
        }
    }
}

// ---------------- kernel 3: sparse aggregation over fp16 x ----------------
// Reads the fp16 shadow (half the L2 bytes), accumulates fp32, writes fp16 Ah.
__global__ void __launch_bounds__(128) agg_kernel() {
    __shared__ uint32_t rowbits[ADJ_WORDS];
    __shared__ int s_off[ADJ_WORDS];
    __shared__ int s_nbr[512];
    __shared__ int s_cnt;
    const int b = blockIdx.y;
    const int n = blockIdx.x;
    const int t = threadIdx.x;

    const uint32_t* row = &g_adj[((size_t)b * NN + n) * ADJ_WORDS];
    if (t < ADJ_WORDS) rowbits[t] = row[t];
    __syncthreads();

    if (t == 0) {
        int off = 0;
        #pragma unroll
        for (int w = 0; w < ADJ_WORDS; w++) { s_off[w] = off; off += __popc(rowbits[w]); }
        s_cnt = off;
    }
    __syncthreads();
    if (t < ADJ_WORDS) {
        uint32_t bits = rowbits[t];
        int pos = s_off[t];
        while (bits) {
            const int bit = __ffs(bits) - 1;
            bits &= bits - 1;
            s_nbr[pos++] = (t << 5) + bit;
        }
    }
    __syncthreads();

    const int deg = s_cnt;
    // each thread owns 4 features: one uint2 (4 halves) per neighbor
    const uint2* xb = (const uint2*)(g_xh + (size_t)b * NN * HH);
    float4 acc = make_float4(0.f, 0.f, 0.f, 0.f);
    for (int i = 0; i < deg; i++) {
        const uint2 v = __ldg(&xb[(size_t)s_nbr[i] * (HH/4) + t]);
        const float2 f01 = __half22float2(*(const __half2*)&v.x);
        const float2 f23 = __half22float2(*(const __half2*)&v.y);
        acc.x += f01.x; acc.y += f01.y; acc.z += f23.x; acc.w += f23.y;
    }

    __half2 h01 = __halves2half2(__float2half_rn(acc.x), __float2half_rn(acc.y));
    __half2 h23 = __halves2half2(__float2half_rn(acc.z), __float2half_rn(acc.w));
    const size_t base = ((size_t)b * NN + n) * (HH/2) + 2 * t;
    ((__half2*)g_Ah)[base]     = h01;
    ((__half2*)g_Ah)[base + 1] = h23;
}

// ---------------- kernel 4: 3-stage cp.async fp16 GEMM + LN, K-chunk 32 ----
// CTA: 64 rows x 512 cols, 512 threads = 16 warps (2 M x 8 N), warp tile 32x64.
// Smem rows padded to 40 halves (80 B). Per-stage: A 0 (5120 B), W 5120 (40960 B).
// Stage = 46080 B, 3 stages, ONE __syncthreads per chunk.
#define STG      46080
#define SG_BIAS  138240                // 512 f
#define SG_GAMMA 140288
#define SG_BETA  142336
#define SG_PSUM  144384                // 64 x 8 f
#define SG_PSQ   146432
#define SG_MU    148480                // 64 f
#define SG_RS    148736
#define SM_TOTAL2 148992

__global__ void __launch_bounds__(512, 1) gemm_mma_kernel(
    const __half* __restrict__ Ah,
    const __half* __restrict__ Wh,
    const float* __restrict__ bl, const float* __restrict__ gl, const float* __restrict__ btl,
    const float* __restrict__ resid, float* __restrict__ out, __half* __restrict__ outh)
{
    extern __shared__ char smem[];
    const uint32_t sbase = smem_u32(smem);
    const int tid  = threadIdx.x;
    const int lane = tid & 31;
    const int wid  = tid >> 5;
    const int mwarp = wid >> 3;        // 0..1
    const int nwarp = wid & 7;         // 0..7
    const int row0 = blockIdx.x * 64;

    ((float*)(smem + SG_BIAS))[tid]  = __ldg(&bl[tid]);
    ((float*)(smem + SG_GAMMA))[tid] = __ldg(&gl[tid]);
    ((float*)(smem + SG_BETA))[tid]  = __ldg(&btl[tid]);

    float c[16][4];
    #pragma unroll
    for (int f = 0; f < 16; f++)
        #pragma unroll
        for (int q = 0; q < 4; q++) c[f][q] = 0.f;

    #define LOAD_CHUNK(chk, stg) do {                                              \
        const int kc0_ = (chk) * 32;                                               \
        const uint32_t sb_ = sbase + (stg) * STG;                                  \
        if (tid < 256) {                                                           \
            const int r_ = tid >> 2, seg_ = tid & 3;                               \
            cpa16(sb_ + r_ * 80 + seg_ * 16,                                       \
                  Ah + (size_t)(row0 + r_) * HH + kc0_ + seg_ * 8);                \
        }                                                                          \
        _Pragma("unroll")                                                          \
        for (int i_ = 0; i_ < 4; i_++) {                                           \
            const int idx_ = tid + i_ * 512;                                       \
            const int r_ = idx_ >> 2, seg_ = idx_ & 3;                             \
            cpa16(sb_ + 5120 + r_ * 80 + seg_ * 16,                                \
                  Wh + (size_t)r_ * HH + kc0_ + seg_ * 8);                         \
        }                                                                          \
        asm volatile("cp.async.commit_group;");                                    \
    } while (0)

    LOAD_CHUNK(0, 0);
    LOAD_CHUNK(1, 1);

    for (int chk = 0; chk < 16; chk++) {
        asm volatile("cp.async.wait_group 1;");
        __syncthreads();
        if (chk + 2 < 16) LOAD_CHUNK(chk + 2, (chk + 2) % 3);

        const uint32_t sb = sbase + (chk % 3) * STG;
        #pragma unroll
        for (int ks = 0; ks < 2; ks++) {
            const int amat = lane >> 3;
            const int arow = (amat & 1) * 8 + (lane & 7);
            const int akb  = (ks * 16 + (amat >> 1) * 8) * 2;
            uint32_t ah[2][4], bb[8][2];
            #pragma unroll
            for (int mi = 0; mi < 2; mi++) {
                const uint32_t ra = mwarp * 32 + mi * 16 + arow;
                ldm_x4(ah[mi], sb + ra * 80 + akb);
            }
            const int bmat = lane >> 3;
            const int bn   = (bmat >> 1) * 8 + (lane & 7);
            const int bkb  = (ks * 16 + (bmat & 1) * 8) * 2;
            #pragma unroll
            for (int g = 0; g < 4; g++) {
                uint32_t r[4];
                ldm_x4(r, sb + 5120 + (uint32_t)(nwarp * 64 + g * 16 + bn) * 80 + bkb);
                bb[g*2][0] = r[0]; bb[g*2][1] = r[1];
                bb[g*2+1][0] = r[2]; bb[g*2+1][1] = r[3];
            }
            #pragma unroll
            for (int mi = 0; mi < 2; mi++)
                #pragma unroll
                for (int ni = 0; ni < 8; ni++) mma_fp16(c[mi*8+ni], ah[mi], bb[ni]);
        }
    }
    // last chunk's stage is not reused; no trailing sync needed before epilogue
    // (each thread's c[] is private; smem epilogue arrays are distinct from stages)

    // ---------------- epilogue: bias + LN + ReLU + residual + fp16 shadow ----
    float* bias_s  = (float*)(smem + SG_BIAS);
    float* gamma_s = (float*)(smem + SG_GAMMA);
    float* beta_s  = (float*)(smem + SG_BETA);
    float* psum_s  = (float*)(smem + SG_PSUM);
    float* psq_s   = (float*)(smem + SG_PSQ);
    float* mu_s    = (float*)(smem + SG_MU);
    float* rs_s    = (float*)(smem + SG_RS);

    float ps[2][2] = {{0.f,0.f},{0.f,0.f}};
    float pq[2][2] = {{0.f,0.f},{0.f,0.f}};
    #pragma unroll
    for (int mi = 0; mi < 2; mi++)
        #pragma unroll
        for (int ni = 0; ni < 8; ni++) {
            const int f = mi*8 + ni;
            #pragma unroll
            for (int h = 0; h < 2; h++)
                #pragma unroll
                for (int j = 0; j < 2; j++) {
                    const int col = nwarp*64 + ni*8 + (lane & 3)*2 + j;
                    const float v = c[f][h*2+j] + bias_s[col];
                    c[f][h*2+j] = v;
                    ps[mi][h] += v;
                    pq[mi][h] += v * v;
                }
        }
    #pragma unroll
    for (int mi = 0; mi < 2; mi++)
        #pragma unroll
        for (int h = 0; h < 2; h++) {
            #pragma unroll
            for (int off = 1; off < 4; off <<= 1) {
                ps[mi][h] += __shfl_xor_sync(0xffffffffu, ps[mi][h], off);
                pq[mi][h] += __shfl_xor_sync(0xffffffffu, pq[mi][h], off);
            }
        }
    if ((lane & 3) == 0) {
        #pragma unroll
        for (int mi = 0; mi < 2; mi++)
            #pragma unroll
            for (int h = 0; h < 2; h++) {
                const int rl = mwarp*32 + mi*16 + h*8 + (lane >> 2);
                psum_s[rl*8 + nwarp] = ps[mi][h];
                psq_s [rl*8 + nwarp] = pq[mi][h];
            }
    }
    __syncthreads();
    if (tid < 64) {
        float s = 0.f, q = 0.f;
        #pragma unroll
        for (int w = 0; w < 8; w++) { s += psum_s[tid*8 + w]; q += psq_s[tid*8 + w]; }
        const float mu = s * (1.0f / HH);
        const float var = q * (1.0f / HH) - mu * mu;
        mu_s[tid] = mu;
        rs_s[tid] = rsqrtf(var + LN_EPS);
    }
    __syncthreads();

    #pragma unroll
    for (int mi = 0; mi < 2; mi++)
        #pragma unroll
        for (int h = 0; h < 2; h++) {
            const int rl = mwarp*32 + mi*16 + h*8 + (lane >> 2);
            const int grow = row0 + rl;
            const float mu = mu_s[rl];
            const float rs = rs_s[rl];
            #pragma unroll
            for (int ni = 0; ni < 8; ni++) {
                const int f = mi*8 + ni;
                const int col = nwarp*64 + ni*8 + (lane & 3)*2;
                float2 o;
                o.x = fmaxf((c[f][h*2+0] - mu) * rs * gamma_s[col]   + beta_s[col],   0.f);
                o.y = fmaxf((c[f][h*2+1] - mu) * rs * gamma_s[col+1] + beta_s[col+1], 0.f);
                if (resid != nullptr) {
                    const float2 rv = __ldg((const float2*)&resid[(size_t)grow * HH + col]);
                    o.x += rv.x; o.y += rv.y;
                }
                *(float2*)&out[(size_t)grow * HH + col] = o;
                *(__half2*)&outh[(size_t)grow * HH + col] = __floats2half2_rn(o.x, o.y);
            }
        }
}

// ---------------- launcher ----------------
extern "C" void kernel_launch(void* const* d_in, const int* in_sizes, int n_in,
                              void* d_out, int out_size) {
    (void)in_sizes; (void)n_in; (void)out_size;
    const float*  node_features = (const float*)d_in[0];   // [8,2048,512]
    const float2* coords        = (const float2*)d_in[1];  // [8,2048,2]
    const float*  W             = (const float*)d_in[2];   // [3,512,512]
    const float*  bvec          = (const float*)d_in[3];   // [3,512]
    const float*  gamma         = (const float*)d_in[4];   // [3,512]
    const float*  beta          = (const float*)d_in[5];   // [3,512]
    float*        outp          = (float*)d_out;           // [8,2048,512]

    float4* gx;  cudaGetSymbolAddress((void**)&gx,  g_x4);
    __half *ah, *wh, *xh;
    cudaGetSymbolAddress((void**)&ah, g_Ah);
    cudaGetSymbolAddress((void**)&wh, g_Wh);
    cudaGetSymbolAddress((void**)&xh, g_xh);

    cudaFuncSetAttribute(gemm_mma_kernel, cudaFuncAttributeMaxDynamicSharedMemorySize, SM_TOTAL2);

    // launch 0: setup (zero adj + convw + node_features->fp16)
    setup_kernel<<<1920, 256>>>(W, (const float4*)node_features);
    topk_adj_kernel<<<dim3(NN / 8, BB), 256>>>(coords);

    for (int l = 0; l < NLAYERS; l++) {
        agg_kernel<<<dim3(NN, BB), 128>>>();

        const float* resid = (l == 0) ? nullptr : (const float*)gx;
        float* out = (l == NLAYERS - 1) ? outp : (float*)gx;
        gemm_mma_kernel<<<MTOT / 64, 512, SM_TOTAL2>>>(
            ah, wh + (size_t)l * HH * HH,
            bvec + (size_t)l * HH, gamma + (size_t)l * HH, beta + (size_t)l * HH,
            resid, out, xh);
    }
}